// round 5
// baseline (speedup 1.0000x reference)
#include <cuda_runtime.h>
#include <math.h>

#define NPTS    200000
#define NBINS   512
#define BLOCKS  296       // 2 blocks/SM on 148 SMs, single wave
#define TPB     256
#define WPB     8         // warps per block

// Global accumulator + completion ticket. Invariant: both zero at launch
// start; the last block restores them after writing d_out (graph-replay safe).
__device__ float        g_hist[NBINS];
__device__ unsigned int g_ticket;

__device__ __forceinline__ float ex2f(float x) {
    float y;
    asm("ex2.approx.f32 %0, %1;" : "=f"(y) : "f"(x));
    return y;
}
__device__ __forceinline__ float ldcg(const float* p) {
    float v;
    asm volatile("ld.global.cg.f32 %0, [%1];" : "=f"(v) : "l"(p));
    return v;
}

// ---------------------------------------------------------------------------
// Single fused kernel: fold + warp-cooperative scatter into per-warp shared
// hists + block merge -> global atomic hist; last block finalizes output.
// ---------------------------------------------------------------------------
__global__ void __launch_bounds__(TPB, 2) main_kernel(
        const float* __restrict__ means,
        const float* __restrict__ scan_point,
        const float* __restrict__ colours,
        const float* __restrict__ coefficients,
        const float* __restrict__ opacities,
        const float* __restrict__ scales,
        float* __restrict__ out)
{
    __shared__ float  hist[WPB][NBINS];   // 16 KB: per-warp private hist
    __shared__ float4 sp[WPB][32];        //  4 KB: staged (k, mneg, B, A2)
    __shared__ float2 sq[WPB][32];        //  2 KB: staged (I, packed b0|nb)
    __shared__ unsigned int s_last;

    const int w    = threadIdx.x >> 5;
    const int lane = threadIdx.x & 31;

    // zero own warp's hist
    #pragma unroll
    for (int t = 0; t < NBINS / 32; ++t) hist[w][lane + 32 * t] = 0.0f;
    __syncwarp();

    const int chunk  = (NPTS + BLOCKS - 1) / BLOCKS;   // 676
    const int bstart = blockIdx.x * chunk;
    const int bend   = min(NPTS, bstart + chunk);
    const int wchunk = (chunk + WPB - 1) / WPB;        // 85
    const int wstart = bstart + w * wchunk;
    const int wend   = min(bend, wstart + wchunk);

    const float sx = scan_point[0], sy = scan_point[1], sz = scan_point[2];

    for (int t = wstart; t < wend; t += 32) {
        // ---- fold phase: lane -> one point ----
        int p = t + lane;
        float4 P  = make_float4(0.f, 0.f, 0.f, 0.f);
        float  I  = 0.f;
        int    pk = 0;
        if (p < wend) {
            float dx = means[3 * p + 0] - sx;
            float dy = means[3 * p + 1] - sy;
            float dz = means[3 * p + 2] - sz;
            float r0 = sqrtf(fmaf(dx, dx, fmaf(dy, dy, dz * dz)));

            float sigma = fmaxf(__expf(scales[p]), 0.005f);   // BIN_RES/2
            float sinv  = __frcp_rn(sigma);

            float coeff = __frcp_rn(1.0f + __expf(-coefficients[p]));

            float op = opacities[p];
            float co = colours[p];
            I = (op * op) * (co * co);

            // pdf*(h/2) = e * (A + B*(r-r0));  gg = fma(r, B, A2)
            float A  = 0.005f * 0.3989422804014327f * coeff * sinv;
            float B  = 0.005f * (1.0f - coeff) * sinv * sinv;
            float A2 = A - B * r0;

            // e = 2^(-(d*k)^2), k = sinv*sqrt(0.5*log2 e)
            float k    = 0.84932180028802f * sinv;
            float mneg = -r0 * k;
            P = make_float4(k, mneg, B, A2);

            // support window: 4.41647/k ~ 5.2 sigma (tail < 1.4e-6, invisible)
            float W   = 4.41647f / k;
            int b0 = max(0,   (int)ceilf ((r0 - W) * 200.0f - 1.0f));
            int b1 = min(511, (int)floorf((r0 + W) * 200.0f - 1.0f));
            int nb = max(0, b1 - b0 + 1);
            pk = b0 | (nb << 16);
        }
        sp[w][lane] = P;
        sq[w][lane] = make_float2(I, __int_as_float(pk));
        __syncwarp();

        // ---- scatter phase: warp sweeps each point's bin window ----
        const int cnt = min(32, wend - t);
        for (int j = 0; j < cnt; ++j) {
            float2 iq = sq[w][j];
            int pkj = __float_as_int(iq.y);
            int nb  = pkj >> 16;
            if (nb == 0) continue;                // warp-uniform
            float4 q  = sp[w][j];
            int   b0  = pkj & 0xFFFF;
            float Ij  = iq.x;
            float rt  = 0.005f * (float)(b0 + lane + 1);
            int   b   = b0 + lane;
            const int full = nb >> 5;             // iterations with all lanes active
            for (int s = 0; s < full; ++s) {
                float u  = fmaf(rt, q.x, q.y);
                float e  = ex2f(-u * u);
                float gg = fmaf(rt, q.z, q.w);
                float pr = __saturatef(e * gg);
                hist[w][b] = fmaf(Ij, pr, hist[w][b]);
                rt += 0.16f;                      // 32 * 0.005
                b  += 32;
            }
            if ((full << 5) + lane < nb) {        // predicated tail
                float u  = fmaf(rt, q.x, q.y);
                float e  = ex2f(-u * u);
                float gg = fmaf(rt, q.z, q.w);
                float pr = __saturatef(e * gg);
                hist[w][b] = fmaf(Ij, pr, hist[w][b]);
            }
        }
        __syncwarp();
    }

    // ---- merge 8 warp hists -> atomic add into global hist ----
    __syncthreads();
    #pragma unroll
    for (int b = threadIdx.x; b < NBINS; b += TPB) {
        float s = 0.0f;
        #pragma unroll
        for (int ww = 0; ww < WPB; ++ww) s += hist[ww][b];
        atomicAdd(&g_hist[b], s);
    }

    // ---- last-block finalize (no spinning: only the final arrival acts) ----
    __threadfence();
    if (threadIdx.x == 0)
        s_last = atomicAdd(&g_ticket, 1u);
    __syncthreads();

    if (s_last == BLOCKS - 1) {
        __threadfence();
        #pragma unroll
        for (int b = threadIdx.x; b < NBINS; b += TPB) {
            float v = ldcg(&g_hist[b]);
            float r = 0.005f * (float)(b + 1);
            out[b] = v / (r * r);
            g_hist[b] = 0.0f;                     // restore invariant
        }
        __threadfence();
        __syncthreads();
        if (threadIdx.x == 0) g_ticket = 0u;      // restore invariant
    }
}

// ---------------------------------------------------------------------------
extern "C" void kernel_launch(void* const* d_in, const int* in_sizes, int n_in,
                              void* d_out, int out_size)
{
    const float* means        = (const float*)d_in[0];
    const float* scan_point   = (const float*)d_in[1];
    const float* colours      = (const float*)d_in[2];
    const float* coefficients = (const float*)d_in[3];
    const float* opacities    = (const float*)d_in[4];
    const float* scales       = (const float*)d_in[5];

    float* out = (float*)d_out;

    main_kernel<<<BLOCKS, TPB>>>(means, scan_point, colours,
                                 coefficients, opacities, scales, out);
}

// round 6
// speedup vs baseline: 1.2351x; 1.2351x over previous
#include <cuda_runtime.h>
#include <math.h>

#define NPTS    200000
#define NBINS   512
#define BLOCKS  592       // 4 blocks/SM on 148 SMs, single wave
#define TPB     256
#define WPB     8         // warps per block
#define NCOPY   16        // global hist copies (de-contended atomics)

// Global accumulators + completion ticket. Invariant: all zero at launch
// start; the last block restores them after writing d_out (graph-replay safe).
__device__ float        g_hist[NCOPY][NBINS];
__device__ unsigned int g_ticket;

__device__ __forceinline__ float ex2f(float x) {
    float y;
    asm("ex2.approx.f32 %0, %1;" : "=f"(y) : "f"(x));
    return y;
}
__device__ __forceinline__ float ldcg(const float* p) {
    float v;
    asm volatile("ld.global.cg.f32 %0, [%1];" : "=f"(v) : "l"(p));
    return v;
}

// ---------------------------------------------------------------------------
// Single fused kernel: fold + warp-cooperative scatter into per-warp shared
// hists + block merge -> 16-way global hist; last block finalizes output.
// ---------------------------------------------------------------------------
__global__ void __launch_bounds__(TPB, 4) main_kernel(
        const float* __restrict__ means,
        const float* __restrict__ scan_point,
        const float* __restrict__ colours,
        const float* __restrict__ coefficients,
        const float* __restrict__ opacities,
        const float* __restrict__ scales,
        float* __restrict__ out)
{
    __shared__ float  hist[WPB][NBINS];   // 16 KB: per-warp private hist
    __shared__ float4 sp[WPB][32];        //  4 KB: staged (k, mneg, B, A2)
    __shared__ float2 sq[WPB][32];        //  2 KB: staged (I, packed b0|nb)
    __shared__ unsigned int s_last;

    const int w    = threadIdx.x >> 5;
    const int lane = threadIdx.x & 31;

    // zero own warp's hist
    #pragma unroll
    for (int t = 0; t < NBINS / 32; ++t) hist[w][lane + 32 * t] = 0.0f;
    __syncwarp();

    const int chunk  = (NPTS + BLOCKS - 1) / BLOCKS;   // 338
    const int bstart = blockIdx.x * chunk;
    const int bend   = min(NPTS, bstart + chunk);
    const int wchunk = (chunk + WPB - 1) / WPB;        // 43
    const int wstart = bstart + w * wchunk;
    const int wend   = min(bend, wstart + wchunk);

    const float sx = scan_point[0], sy = scan_point[1], sz = scan_point[2];

    for (int t = wstart; t < wend; t += 32) {
        // ---- fold phase: lane -> one point ----
        int p = t + lane;
        float4 P  = make_float4(0.f, 0.f, 0.f, 0.f);
        float  I  = 0.f;
        int    pk = 0;
        if (p < wend) {
            float dx = means[3 * p + 0] - sx;
            float dy = means[3 * p + 1] - sy;
            float dz = means[3 * p + 2] - sz;
            float r0 = sqrtf(fmaf(dx, dx, fmaf(dy, dy, dz * dz)));

            float sigma = fmaxf(__expf(scales[p]), 0.005f);   // BIN_RES/2
            float sinv  = __frcp_rn(sigma);

            float coeff = __frcp_rn(1.0f + __expf(-coefficients[p]));

            float op = opacities[p];
            float co = colours[p];
            I = (op * op) * (co * co);

            // pdf*(h/2) = e * (A + B*(r-r0));  gg = fma(r, B, A2)
            float A  = 0.005f * 0.3989422804014327f * coeff * sinv;
            float B  = 0.005f * (1.0f - coeff) * sinv * sinv;
            float A2 = A - B * r0;

            // e = 2^(-(d*k)^2), k = sinv*sqrt(0.5*log2 e)
            float k    = 0.84932180028802f * sinv;
            float mneg = -r0 * k;
            P = make_float4(k, mneg, B, A2);

            // support window: 3.60947/k = 4.25 sigma (trunc mass 2e-5 << 1e-3)
            float W   = 3.60947f / k;
            int b0 = max(0,   (int)ceilf ((r0 - W) * 200.0f - 1.0f));
            int b1 = min(511, (int)floorf((r0 + W) * 200.0f - 1.0f));
            int nb = max(0, b1 - b0 + 1);
            pk = b0 | (nb << 16);
        }
        sp[w][lane] = P;
        sq[w][lane] = make_float2(I, __int_as_float(pk));
        __syncwarp();

        // ---- scatter phase: warp sweeps each point's bin window ----
        const int cnt = min(32, wend - t);
        for (int j = 0; j < cnt; ++j) {
            float2 iq = sq[w][j];
            int pkj = __float_as_int(iq.y);
            int nb  = pkj >> 16;
            if (nb == 0) continue;                // warp-uniform
            float4 q  = sp[w][j];
            int   b0  = pkj & 0xFFFF;
            float Ij  = iq.x;
            float rt  = 0.005f * (float)(b0 + lane + 1);
            int   b   = b0 + lane;
            const int full = nb >> 5;             // all-lane iterations
            for (int s = 0; s < full; ++s) {
                float u  = fmaf(rt, q.x, q.y);
                float e  = ex2f(-u * u);
                float gg = fmaf(rt, q.z, q.w);
                float pr = __saturatef(e * gg);
                hist[w][b] = fmaf(Ij, pr, hist[w][b]);
                rt += 0.16f;                      // 32 * 0.005
                b  += 32;
            }
            if ((full << 5) + lane < nb) {        // predicated tail
                float u  = fmaf(rt, q.x, q.y);
                float e  = ex2f(-u * u);
                float gg = fmaf(rt, q.z, q.w);
                float pr = __saturatef(e * gg);
                hist[w][b] = fmaf(Ij, pr, hist[w][b]);
            }
        }
        __syncwarp();
    }

    // ---- merge 8 warp hists -> one of 16 global copies (37 conflicts/addr) ----
    __syncthreads();
    float* __restrict__ gh = g_hist[blockIdx.x & (NCOPY - 1)];
    #pragma unroll
    for (int b = threadIdx.x; b < NBINS; b += TPB) {
        float s = 0.0f;
        #pragma unroll
        for (int ww = 0; ww < WPB; ++ww) s += hist[ww][b];
        atomicAdd(&gh[b], s);
    }

    // ---- last-block finalize (no spinning: only the final arrival acts) ----
    __threadfence();
    if (threadIdx.x == 0)
        s_last = atomicAdd(&g_ticket, 1u);
    __syncthreads();

    if (s_last == BLOCKS - 1) {
        __threadfence();
        #pragma unroll
        for (int b = threadIdx.x; b < NBINS; b += TPB) {
            float v = 0.0f;
            #pragma unroll
            for (int c = 0; c < NCOPY; ++c) {
                v += ldcg(&g_hist[c][b]);
                g_hist[c][b] = 0.0f;              // restore invariant
            }
            float r = 0.005f * (float)(b + 1);
            out[b] = v / (r * r);
        }
        __threadfence();
        __syncthreads();
        if (threadIdx.x == 0) g_ticket = 0u;      // restore invariant
    }
}

// ---------------------------------------------------------------------------
extern "C" void kernel_launch(void* const* d_in, const int* in_sizes, int n_in,
                              void* d_out, int out_size)
{
    const float* means        = (const float*)d_in[0];
    const float* scan_point   = (const float*)d_in[1];
    const float* colours      = (const float*)d_in[2];
    const float* coefficients = (const float*)d_in[3];
    const float* opacities    = (const float*)d_in[4];
    const float* scales       = (const float*)d_in[5];

    float* out = (float*)d_out;

    main_kernel<<<BLOCKS, TPB>>>(means, scan_point, colours,
                                 coefficients, opacities, scales, out);
}

// round 7
// speedup vs baseline: 1.2514x; 1.0132x over previous
#include <cuda_runtime.h>
#include <math.h>

#define NPTS    200000
#define NBINS   512
#define BLOCKS  888       // 6 blocks/SM on 148 SMs, single wave
#define TPB     256
#define WPB     8         // warps per block
#define NCOPY   32        // global hist copies (de-contended atomics)

// Global accumulators + completion ticket. Invariant: all zero at launch
// start; the last block restores them after writing d_out (graph-replay safe).
__device__ float        g_hist[NCOPY][NBINS];
__device__ unsigned int g_ticket;

__device__ __forceinline__ float ex2f(float x) {
    float y;
    asm("ex2.approx.f32 %0, %1;" : "=f"(y) : "f"(x));
    return y;
}
__device__ __forceinline__ float ldcg(const float* p) {
    float v;
    asm volatile("ld.global.cg.f32 %0, [%1];" : "=f"(v) : "l"(p));
    return v;
}

// ---------------------------------------------------------------------------
// Single fused kernel: fold + warp-cooperative scatter into per-warp shared
// hists + block merge -> 32-way global hist; last block finalizes output.
// ---------------------------------------------------------------------------
__global__ void __launch_bounds__(TPB, 6) main_kernel(
        const float* __restrict__ means,
        const float* __restrict__ scan_point,
        const float* __restrict__ colours,
        const float* __restrict__ coefficients,
        const float* __restrict__ opacities,
        const float* __restrict__ scales,
        float* __restrict__ out)
{
    __shared__ float  hist[WPB][NBINS];   // 16 KB: per-warp private hist
    __shared__ float4 sp[WPB][32];        //  4 KB: staged (k, mneg, B, A2)
    __shared__ float4 sq[WPB][32];        //  4 KB: staged (I, rt0, pk, -)
    __shared__ unsigned int s_last;

    const int   w     = threadIdx.x >> 5;
    const int   lane  = threadIdx.x & 31;
    const float flane = 0.005f * (float)lane;

    // zero own warp's hist
    #pragma unroll
    for (int t = 0; t < NBINS / 32; ++t) hist[w][lane + 32 * t] = 0.0f;
    __syncwarp();

    const int chunk  = (NPTS + BLOCKS - 1) / BLOCKS;   // 226
    const int bstart = blockIdx.x * chunk;
    const int bend   = min(NPTS, bstart + chunk);
    const int wchunk = (chunk + WPB - 1) / WPB;        // 29
    const int wstart = bstart + w * wchunk;
    const int wend   = min(bend, wstart + wchunk);

    const float sx = scan_point[0], sy = scan_point[1], sz = scan_point[2];

    for (int t = wstart; t < wend; t += 32) {
        // ---- fold phase: lane -> one point ----
        int p = t + lane;
        float4 P = make_float4(0.f, 0.f, 0.f, 0.f);
        float  I = 0.f, rt0 = 0.f;
        int    pk = 0;
        if (p < wend) {
            float dx = means[3 * p + 0] - sx;
            float dy = means[3 * p + 1] - sy;
            float dz = means[3 * p + 2] - sz;
            float r0 = sqrtf(fmaf(dx, dx, fmaf(dy, dy, dz * dz)));

            float sigma = fmaxf(__expf(scales[p]), 0.005f);   // BIN_RES/2
            float sinv  = __frcp_rn(sigma);

            float coeff = __frcp_rn(1.0f + __expf(-coefficients[p]));

            float op = opacities[p];
            float co = colours[p];
            I = (op * op) * (co * co);

            // pdf*(h/2) = e * (A + B*(r-r0));  gg = fma(r, B, A2)
            float A  = 0.005f * 0.3989422804014327f * coeff * sinv;
            float B  = 0.005f * (1.0f - coeff) * sinv * sinv;
            float A2 = A - B * r0;

            // e = 2^(-(d*k)^2), k = sinv*sqrt(0.5*log2 e)
            float k    = 0.84932180028802f * sinv;
            float mneg = -r0 * k;
            P = make_float4(k, mneg, B, A2);

            // support window: 3.39729/k = 4.0 sigma (trunc mass ~6e-5 << 1e-3)
            float W   = 3.39729f / k;
            int b0 = max(0,   (int)ceilf ((r0 - W) * 200.0f - 1.0f));
            int b1 = min(511, (int)floorf((r0 + W) * 200.0f - 1.0f));
            int nb = max(0, b1 - b0 + 1);
            pk  = b0 | (nb << 16);
            rt0 = 0.005f * (float)(b0 + 1);
        }
        sp[w][lane] = P;
        sq[w][lane] = make_float4(I, rt0, __int_as_float(pk), 0.f);
        __syncwarp();

        // ---- scatter phase: warp sweeps each point's bin window ----
        const int cnt = min(32, wend - t);
        for (int j = 0; j < cnt; ++j) {
            float4 iq = sq[w][j];
            int pkj = __float_as_int(iq.z);
            int nb  = pkj >> 16;
            if (nb == 0) continue;                 // warp-uniform
            float4 q  = sp[w][j];
            int   b   = (pkj & 0xFFFF) + lane;
            float Ij  = iq.x;
            float rt  = iq.y + flane;

            // step 0: bins [b0, b0+32)
            {
                float u  = fmaf(rt, q.x, q.y);
                float e  = ex2f(-u * u);
                float gg = fmaf(rt, q.z, q.w);
                float pr = __saturatef(e * gg);
                if (lane < nb)
                    hist[w][b] = fmaf(Ij, pr, hist[w][b]);
            }
            // step 1: bins [b0+32, b0+64)  (warp-uniform guard)
            if (nb > 32) {
                float rt1 = rt + 0.16f;
                float u  = fmaf(rt1, q.x, q.y);
                float e  = ex2f(-u * u);
                float gg = fmaf(rt1, q.z, q.w);
                float pr = __saturatef(e * gg);
                if (lane + 32 < nb)
                    hist[w][b + 32] = fmaf(Ij, pr, hist[w][b + 32]);
            }
            // rare tail: nb > 64
            if (nb > 64) {
                float rts = rt + 0.32f;
                int   bs  = b + 64;
                for (int done = 64; done < nb; done += 32) {
                    float u  = fmaf(rts, q.x, q.y);
                    float e  = ex2f(-u * u);
                    float gg = fmaf(rts, q.z, q.w);
                    float pr = __saturatef(e * gg);
                    if (done + lane < nb)
                        hist[w][bs] = fmaf(Ij, pr, hist[w][bs]);
                    rts += 0.16f;
                    bs  += 32;
                }
            }
        }
        __syncwarp();
    }

    // ---- merge 8 warp hists -> one of 32 global copies (~28 conflicts/addr) ----
    __syncthreads();
    float* __restrict__ gh = g_hist[blockIdx.x & (NCOPY - 1)];
    #pragma unroll
    for (int b = threadIdx.x; b < NBINS; b += TPB) {
        float s = 0.0f;
        #pragma unroll
        for (int ww = 0; ww < WPB; ++ww) s += hist[ww][b];
        atomicAdd(&gh[b], s);
    }

    // ---- last-block finalize (no spinning: only the final arrival acts) ----
    __threadfence();
    if (threadIdx.x == 0)
        s_last = atomicAdd(&g_ticket, 1u);
    __syncthreads();

    if (s_last == BLOCKS - 1) {
        __threadfence();
        #pragma unroll
        for (int b = threadIdx.x; b < NBINS; b += TPB) {
            float v = 0.0f;
            #pragma unroll
            for (int c = 0; c < NCOPY; ++c) {
                v += ldcg(&g_hist[c][b]);
                g_hist[c][b] = 0.0f;              // restore invariant
            }
            float r = 0.005f * (float)(b + 1);
            out[b] = v / (r * r);
        }
        __threadfence();
        __syncthreads();
        if (threadIdx.x == 0) g_ticket = 0u;      // restore invariant
    }
}

// ---------------------------------------------------------------------------
extern "C" void kernel_launch(void* const* d_in, const int* in_sizes, int n_in,
                              void* d_out, int out_size)
{
    const float* means        = (const float*)d_in[0];
    const float* scan_point   = (const float*)d_in[1];
    const float* colours      = (const float*)d_in[2];
    const float* coefficients = (const float*)d_in[3];
    const float* opacities    = (const float*)d_in[4];
    const float* scales       = (const float*)d_in[5];

    float* out = (float*)d_out;

    main_kernel<<<BLOCKS, TPB>>>(means, scan_point, colours,
                                 coefficients, opacities, scales, out);
}

// round 8
// speedup vs baseline: 1.4646x; 1.1704x over previous
#include <cuda_runtime.h>
#include <math.h>

#define NPTS    200000
#define NBINS   512
#define BLOCKS  888       // 6 blocks/SM on 148 SMs, single wave
#define TPB     256
#define WPB     8         // warps per block
#define NCOPY   32        // global hist copies (de-contended atomics)

// Global accumulators + completion ticket. Invariant: all zero at launch
// start; the last block restores them after writing d_out (graph-replay safe).
__device__ float        g_hist[NCOPY][NBINS];
__device__ unsigned int g_ticket;

__device__ __forceinline__ float ex2f(float x) {
    float y;
    asm("ex2.approx.f32 %0, %1;" : "=f"(y) : "f"(x));
    return y;
}
__device__ __forceinline__ float ldcg(const float* p) {
    float v;
    asm volatile("ld.global.cg.f32 %0, [%1];" : "=f"(v) : "l"(p));
    return v;
}

// ---------------------------------------------------------------------------
// Single fused kernel. Key math: pdf = e*(A + B(r-r0)) with B>0, so
// clip-at-0 is exactly the bound r >= r0 - A/B (~0.4 sigma). The left
// Gaussian tail is therefore dead weight: window = [r0 - min(4sig, A/B),
// r0 + 4sig], ~44 bins instead of 80, with NO extra error from the left side.
// Upper clip never fires (max pr ~0.067 for sigma >= 0.035).
// ---------------------------------------------------------------------------
__global__ void __launch_bounds__(TPB, 6) main_kernel(
        const float* __restrict__ means,
        const float* __restrict__ scan_point,
        const float* __restrict__ colours,
        const float* __restrict__ coefficients,
        const float* __restrict__ opacities,
        const float* __restrict__ scales,
        float* __restrict__ out)
{
    __shared__ float  hist[WPB][NBINS];   // 16 KB: per-warp private hist
    __shared__ float4 sp[WPB][32];        //  4 KB: staged (k, mneg, B, A2)
    __shared__ float4 sq[WPB][32];        //  4 KB: staged (I, rt0, pk, -)
    __shared__ unsigned int s_last;

    const int   w     = threadIdx.x >> 5;
    const int   lane  = threadIdx.x & 31;
    const float flane = 0.005f * (float)lane;

    // zero own warp's hist
    #pragma unroll
    for (int t = 0; t < NBINS / 32; ++t) hist[w][lane + 32 * t] = 0.0f;
    __syncwarp();

    const int chunk  = (NPTS + BLOCKS - 1) / BLOCKS;   // 226
    const int bstart = blockIdx.x * chunk;
    const int bend   = min(NPTS, bstart + chunk);
    const int wchunk = (chunk + WPB - 1) / WPB;        // 29
    const int wstart = bstart + w * wchunk;
    const int wend   = min(bend, wstart + wchunk);

    const float sx = scan_point[0], sy = scan_point[1], sz = scan_point[2];

    for (int t = wstart; t < wend; t += 32) {
        // ---- fold phase: lane -> one point; ballot-compact active points ----
        int p = t + lane;
        float4 P = make_float4(0.f, 0.f, 0.f, 0.f);
        float  I = 0.f, rt0 = 0.f;
        int    pk = 0;
        if (p < wend) {
            float dx = means[3 * p + 0] - sx;
            float dy = means[3 * p + 1] - sy;
            float dz = means[3 * p + 2] - sz;
            float r0 = sqrtf(fmaf(dx, dx, fmaf(dy, dy, dz * dz)));

            float sigma = fmaxf(__expf(scales[p]), 0.005f);   // BIN_RES/2
            float sinv  = __frcp_rn(sigma);

            float coeff = __frcp_rn(1.0f + __expf(-coefficients[p]));

            float op = opacities[p];
            float co = colours[p];
            I = (op * op) * (co * co);

            // pdf*(h/2) = e * (A + B*(r-r0));  gg = fma(r, B, A2)
            float A  = 0.005f * 0.3989422804014327f * coeff * sinv;
            float B  = 0.005f * (1.0f - coeff) * sinv * sinv;
            float A2 = A - B * r0;

            // e = 2^(-(d*k)^2), k = sinv*sqrt(0.5*log2 e)
            float k    = 0.84932180028802f * sinv;
            float mneg = -r0 * k;
            P = make_float4(k, mneg, B, A2);

            // window: left edge = clip zero-crossing r0 - A/B (exact),
            //         capped by 4-sigma Gaussian cut; right edge = 4 sigma.
            float W    = 3.39729f / k;            // 4 sigma in r units
            float AoB  = A * __frcp_rn(B);        // ~0.4 sigma
            float lo   = r0 - fminf(W, AoB);
            float hi   = r0 + W;
            int b0 = max(0,   (int)ceilf (lo * 200.0f - 1.0f));
            int b1 = min(511, (int)floorf(hi * 200.0f - 1.0f));
            int nb = max(0, b1 - b0 + 1);
            pk  = b0 | (nb << 16);
            rt0 = 0.005f * (float)(b0 + 1);
        }
        // compact: only points with nb>0 enter staging
        bool     act = (pk >> 16) != 0;
        unsigned m   = __ballot_sync(0xFFFFFFFFu, act);
        if (act) {
            int pos = __popc(m & ((1u << lane) - 1u));
            sp[w][pos] = P;
            sq[w][pos] = make_float4(I, rt0, __int_as_float(pk), 0.f);
        }
        const int cnt = __popc(m);
        __syncwarp();

        // ---- scatter phase: warp sweeps each active point's bin window ----
        #pragma unroll 2
        for (int j = 0; j < cnt; ++j) {
            float4 iq = sq[w][j];
            float4 q  = sp[w][j];
            int pkj = __float_as_int(iq.z);
            int nb  = pkj >> 16;
            int   b   = (pkj & 0xFFFF) + lane;
            float Ij  = iq.x;
            float rt  = iq.y + flane;

            // step 0: bins [b0, b0+32)
            {
                float u  = fmaf(rt, q.x, q.y);
                float e  = ex2f(-u * u);
                float gg = fmaf(rt, q.z, q.w);
                float pr = __saturatef(e * gg);
                if (lane < nb)
                    hist[w][b] = fmaf(Ij, pr, hist[w][b]);
            }
            // step 1: bins [b0+32, b0+64)  (warp-uniform guard)
            if (nb > 32) {
                float rt1 = rt + 0.16f;
                float u  = fmaf(rt1, q.x, q.y);
                float e  = ex2f(-u * u);
                float gg = fmaf(rt1, q.z, q.w);
                float pr = __saturatef(e * gg);
                if (lane + 32 < nb)
                    hist[w][b + 32] = fmaf(Ij, pr, hist[w][b + 32]);
            }
            // rare tail: nb > 64 (sigma > ~0.073)
            if (nb > 64) {
                float rts = rt + 0.32f;
                int   bs  = b + 64;
                for (int done = 64; done < nb; done += 32) {
                    float u  = fmaf(rts, q.x, q.y);
                    float e  = ex2f(-u * u);
                    float gg = fmaf(rts, q.z, q.w);
                    float pr = __saturatef(e * gg);
                    if (done + lane < nb)
                        hist[w][bs] = fmaf(Ij, pr, hist[w][bs]);
                    rts += 0.16f;
                    bs  += 32;
                }
            }
        }
        __syncwarp();
    }

    // ---- merge 8 warp hists -> one of 32 global copies (~28 conflicts/addr) ----
    __syncthreads();
    float* __restrict__ gh = g_hist[blockIdx.x & (NCOPY - 1)];
    #pragma unroll
    for (int b = threadIdx.x; b < NBINS; b += TPB) {
        float s = 0.0f;
        #pragma unroll
        for (int ww = 0; ww < WPB; ++ww) s += hist[ww][b];
        atomicAdd(&gh[b], s);
    }

    // ---- last-block finalize (no spinning: only the final arrival acts) ----
    __threadfence();
    if (threadIdx.x == 0)
        s_last = atomicAdd(&g_ticket, 1u);
    __syncthreads();

    if (s_last == BLOCKS - 1) {
        __threadfence();
        #pragma unroll
        for (int b = threadIdx.x; b < NBINS; b += TPB) {
            float v = 0.0f;
            #pragma unroll
            for (int c = 0; c < NCOPY; ++c) {
                v += ldcg(&g_hist[c][b]);
                g_hist[c][b] = 0.0f;              // restore invariant
            }
            float r = 0.005f * (float)(b + 1);
            out[b] = v / (r * r);
        }
        __threadfence();
        __syncthreads();
        if (threadIdx.x == 0) g_ticket = 0u;      // restore invariant
    }
}

// ---------------------------------------------------------------------------
extern "C" void kernel_launch(void* const* d_in, const int* in_sizes, int n_in,
                              void* d_out, int out_size)
{
    const float* means        = (const float*)d_in[0];
    const float* scan_point   = (const float*)d_in[1];
    const float* colours      = (const float*)d_in[2];
    const float* coefficients = (const float*)d_in[3];
    const float* opacities    = (const float*)d_in[4];
    const float* scales       = (const float*)d_in[5];

    float* out = (float*)d_out;

    main_kernel<<<BLOCKS, TPB>>>(means, scan_point, colours,
                                 coefficients, opacities, scales, out);
}

// round 9
// speedup vs baseline: 1.4711x; 1.0044x over previous
#include <cuda_runtime.h>
#include <math.h>

#define NPTS    200000
#define NBINS   512
#define TPB     256
#define BLOCKS  ((NPTS + TPB - 1) / TPB)   // 782, one point per thread
#define WPB     8                          // warps per block
#define NCOPY   32                         // global hist copies

// Global accumulators + completion ticket. Invariant: all zero at launch
// start; the last block restores them after writing d_out (graph-replay safe).
__device__ float        g_hist[NCOPY][NBINS];
__device__ unsigned int g_ticket;

__device__ __forceinline__ float ex2f(float x) {
    float y;
    asm("ex2.approx.f32 %0, %1;" : "=f"(y) : "f"(x));
    return y;
}
__device__ __forceinline__ float ldcg(const float* p) {
    float v;
    asm volatile("ld.global.cg.f32 %0, [%1];" : "=f"(v) : "l"(p));
    return v;
}

// ---------------------------------------------------------------------------
// Single fused kernel. pdf = e*(A + B(r-r0)), B>0 => clip-at-0 is exactly
// r >= r0 - A/B; window = [r0 - min(4sig, A/B), r0 + 4sig] (~44 bins).
// Block-wide compaction + round-robin warp assignment for load balance.
// ---------------------------------------------------------------------------
__global__ void __launch_bounds__(TPB, 6) main_kernel(
        const float* __restrict__ means,
        const float* __restrict__ scan_point,
        const float* __restrict__ colours,
        const float* __restrict__ coefficients,
        const float* __restrict__ opacities,
        const float* __restrict__ scales,
        float* __restrict__ out)
{
    __shared__ float  hist[WPB][NBINS];   // 16 KB: per-warp private hist
    __shared__ float4 cp[TPB];            //  4 KB: compacted (k, mneg, B, A2)
    __shared__ float4 cq[TPB];            //  4 KB: compacted (I, rt0, pk, -)
    __shared__ int    s_cnt;
    __shared__ unsigned int s_last;

    const int   tid   = threadIdx.x;
    const int   w     = tid >> 5;
    const int   lane  = tid & 31;
    const float flane = 0.005f * (float)lane;

    // zero own warp's hist; init counter
    #pragma unroll
    for (int t = 0; t < NBINS / 32; ++t) hist[w][lane + 32 * t] = 0.0f;
    if (tid == 0) s_cnt = 0;
    __syncthreads();

    // ---- fold phase: one point per thread ----
    const int p = blockIdx.x * TPB + tid;
    float4 P = make_float4(0.f, 0.f, 0.f, 0.f);
    float  I = 0.f, rt0 = 0.f;
    int    pk = 0;
    if (p < NPTS) {
        float sx = scan_point[0], sy = scan_point[1], sz = scan_point[2];
        float dx = means[3 * p + 0] - sx;
        float dy = means[3 * p + 1] - sy;
        float dz = means[3 * p + 2] - sz;
        float r0 = sqrtf(fmaf(dx, dx, fmaf(dy, dy, dz * dz)));

        float sigma = fmaxf(__expf(scales[p]), 0.005f);   // BIN_RES/2
        float sinv  = __frcp_rn(sigma);

        float coeff = __frcp_rn(1.0f + __expf(-coefficients[p]));

        float op = opacities[p];
        float co = colours[p];
        I = (op * op) * (co * co);

        // pdf*(h/2) = e * (A + B*(r-r0));  gg = fma(r, B, A2)
        float A  = 0.005f * 0.3989422804014327f * coeff * sinv;
        float B  = 0.005f * (1.0f - coeff) * sinv * sinv;
        float A2 = A - B * r0;

        // e = 2^(-(d*k)^2), k = sinv*sqrt(0.5*log2 e)
        float k    = 0.84932180028802f * sinv;
        float mneg = -r0 * k;
        P = make_float4(k, mneg, B, A2);

        // window: left = clip zero-crossing (exact), right = 4 sigma
        float W   = 3.39729f / k;             // 4 sigma in r units
        float AoB = A * __frcp_rn(B);         // ~0.4 sigma
        float lo  = r0 - fminf(W, AoB);
        float hi  = r0 + W;
        int b0 = max(0,   (int)ceilf (lo * 200.0f - 1.0f));
        int b1 = min(511, (int)floorf(hi * 200.0f - 1.0f));
        int nb = max(0, b1 - b0 + 1);
        pk  = b0 | (nb << 16);
        rt0 = 0.005f * (float)(b0 + 1);
    }

    // ---- block-wide compaction (warp-aggregated shared atomics) ----
    bool     act = (pk >> 16) != 0;
    unsigned m   = __ballot_sync(0xFFFFFFFFu, act);
    int base = 0;
    if (lane == 0 && m) base = atomicAdd(&s_cnt, __popc(m));
    base = __shfl_sync(0xFFFFFFFFu, base, 0);
    if (act) {
        int pos = base + __popc(m & ((1u << lane) - 1u));
        cp[pos] = P;
        cq[pos] = make_float4(I, rt0, __int_as_float(pk), 0.f);
    }
    __syncthreads();
    const int cnt = s_cnt;

    // ---- scatter: warps round-robin over the compacted block list ----
    #pragma unroll 2
    for (int j = w; j < cnt; j += WPB) {
        float4 iq = cq[j];
        float4 q  = cp[j];
        int pkj = __float_as_int(iq.z);
        int nb  = pkj >> 16;
        int   b   = (pkj & 0xFFFF) + lane;
        float Ij  = iq.x;
        float rt  = iq.y + flane;

        // step 0: bins [b0, b0+32)
        {
            float u  = fmaf(rt, q.x, q.y);
            float e  = ex2f(-u * u);
            float gg = fmaf(rt, q.z, q.w);
            float pr = __saturatef(e * gg);
            if (lane < nb)
                hist[w][b] = fmaf(Ij, pr, hist[w][b]);
        }
        // step 1: bins [b0+32, b0+64)  (warp-uniform guard)
        if (nb > 32) {
            float rt1 = rt + 0.16f;
            float u  = fmaf(rt1, q.x, q.y);
            float e  = ex2f(-u * u);
            float gg = fmaf(rt1, q.z, q.w);
            float pr = __saturatef(e * gg);
            if (lane + 32 < nb)
                hist[w][b + 32] = fmaf(Ij, pr, hist[w][b + 32]);
        }
        // rare tail: nb > 64
        if (nb > 64) {
            float rts = rt + 0.32f;
            int   bs  = b + 64;
            for (int done = 64; done < nb; done += 32) {
                float u  = fmaf(rts, q.x, q.y);
                float e  = ex2f(-u * u);
                float gg = fmaf(rts, q.z, q.w);
                float pr = __saturatef(e * gg);
                if (done + lane < nb)
                    hist[w][bs] = fmaf(Ij, pr, hist[w][bs]);
                rts += 0.16f;
                bs  += 32;
            }
        }
    }

    // ---- merge 8 warp hists -> one of 32 global copies (~25 conflicts/addr) ----
    __syncthreads();
    float* __restrict__ gh = g_hist[blockIdx.x & (NCOPY - 1)];
    #pragma unroll
    for (int b = tid; b < NBINS; b += TPB) {
        float s = 0.0f;
        #pragma unroll
        for (int ww = 0; ww < WPB; ++ww) s += hist[ww][b];
        atomicAdd(&gh[b], s);
    }

    // ---- last-block finalize (no spinning: only the final arrival acts) ----
    __threadfence();
    if (tid == 0)
        s_last = atomicAdd(&g_ticket, 1u);
    __syncthreads();

    if (s_last == BLOCKS - 1) {
        __threadfence();
        #pragma unroll
        for (int b = tid; b < NBINS; b += TPB) {
            float v = 0.0f;
            #pragma unroll
            for (int c = 0; c < NCOPY; ++c) {
                v += ldcg(&g_hist[c][b]);
                g_hist[c][b] = 0.0f;              // restore invariant
            }
            float r = 0.005f * (float)(b + 1);
            out[b] = v / (r * r);
        }
        __threadfence();
        __syncthreads();
        if (tid == 0) g_ticket = 0u;              // restore invariant
    }
}

// ---------------------------------------------------------------------------
extern "C" void kernel_launch(void* const* d_in, const int* in_sizes, int n_in,
                              void* d_out, int out_size)
{
    const float* means        = (const float*)d_in[0];
    const float* scan_point   = (const float*)d_in[1];
    const float* colours      = (const float*)d_in[2];
    const float* coefficients = (const float*)d_in[3];
    const float* opacities    = (const float*)d_in[4];
    const float* scales       = (const float*)d_in[5];

    float* out = (float*)d_out;

    main_kernel<<<BLOCKS, TPB>>>(means, scan_point, colours,
                                 coefficients, opacities, scales, out);
}